// round 15
// baseline (speedup 1.0000x reference)
#include <cuda_runtime.h>
#include <cuda_fp16.h>
#include <math.h>

#define BB 2
#define TT 2048
#define CC 768
#define HH 12
#define DD 64
#define WIN 256
#define NEGBIG -1.0e30f

// ---------------- scratch ----------------
__device__ __half g_q[BB*HH*TT*DD];      // pre-scaled by 1/8
__device__ __half g_k[BB*HH*TT*DD];
__device__ __half g_v[BB*HH*TT*DD];
__device__ float  g_sel[BB*TT];
__device__ __half g_att[(size_t)BB*TT*CC];
__device__ __half g_x16[(size_t)BB*TT*CC];
__device__ __half g_wa16[(size_t)CC*3*CC];
__device__ __half g_wp16[(size_t)CC*CC];

// ---------------- helpers ----------------
__device__ __forceinline__ unsigned pack2(float a, float b) {
    __half2 h = __floats2half2_rn(a, b);
    return *(unsigned*)&h;
}
__device__ __forceinline__ unsigned smem_u32(const void* p) {
    return (unsigned)__cvta_generic_to_shared(p);
}
__device__ __forceinline__ void ldsm4(unsigned r[4], unsigned addr) {
    asm volatile("ldmatrix.sync.aligned.m8n8.x4.shared.b16 {%0,%1,%2,%3}, [%4];"
        : "=r"(r[0]), "=r"(r[1]), "=r"(r[2]), "=r"(r[3]) : "r"(addr));
}
__device__ __forceinline__ void ldsm4t(unsigned r[4], unsigned addr) {
    asm volatile("ldmatrix.sync.aligned.m8n8.x4.trans.shared.b16 {%0,%1,%2,%3}, [%4];"
        : "=r"(r[0]), "=r"(r[1]), "=r"(r[2]), "=r"(r[3]) : "r"(addr));
}
__device__ __forceinline__ void mma_f16(float c[4], unsigned a0, unsigned a1,
                                        unsigned a2, unsigned a3,
                                        unsigned b0, unsigned b1) {
    asm volatile(
        "mma.sync.aligned.m16n8k16.row.col.f32.f16.f16.f32 "
        "{%0,%1,%2,%3},{%4,%5,%6,%7},{%8,%9},{%0,%1,%2,%3};"
        : "+f"(c[0]), "+f"(c[1]), "+f"(c[2]), "+f"(c[3])
        : "r"(a0), "r"(a1), "r"(a2), "r"(a3), "r"(b0), "r"(b1));
}

// attn K/V tile 64x64 halves: 128B rows, chunk c in 0..7
__device__ __forceinline__ int offKV(int r, int c) {
    return r * 64 + (c ^ (r & 7)) * 8;
}

// ---------------- fp32 -> fp16 pre-convert ----------------
__global__ void cvt_kernel(const float* __restrict__ X, const float* __restrict__ Wa,
                           const float* __restrict__ Wp) {
    int idx = blockIdx.x * blockDim.x + threadIdx.x;
    int stride = gridDim.x * blockDim.x;
    const int nX = BB * TT * CC / 4, nA = CC * 3 * CC / 4, nP = CC * CC / 4;
    for (int i = idx; i < nX; i += stride) {
        float4 v = ((const float4*)X)[i];
        ((uint2*)g_x16)[i] = make_uint2(pack2(v.x, v.y), pack2(v.z, v.w));
    }
    for (int i = idx; i < nA; i += stride) {
        float4 v = ((const float4*)Wa)[i];
        ((uint2*)g_wa16)[i] = make_uint2(pack2(v.x, v.y), pack2(v.z, v.w));
    }
    for (int i = idx; i < nP; i += stride) {
        float4 v = ((const float4*)Wp)[i];
        ((uint2*)g_wp16)[i] = make_uint2(pack2(v.x, v.y), pack2(v.z, v.w));
    }
}

// ---------------- GEMM: 64m x 128n block, K-step 64, 2-stage LDG->STS ----------------
// Stage = A[64m x 64k] (128B rows, XOR swizzle, 8 KB)
//       + B as two [64k x 64n] subtiles (128B rows, XOR swizzle, 8 KB each)
#define STG_BYTES 24576
#define GEMM_SMEM_BYTES (2 * STG_BYTES)   // 48 KB -> 3 CTAs/SM

// ---------------- qkv GEMM + fused sel ----------------
__global__ void __launch_bounds__(256, 3) qkv_gemm(
    const float* __restrict__ bias,
    const float* __restrict__ mamba, const float* __restrict__ lnw, const float* __restrict__ lnb,
    const float* __restrict__ selw, const float* __restrict__ selb, const float* __restrict__ mscale)
{
    extern __shared__ __half smh[];
    int tid = threadIdx.x;

    if (blockIdx.x == 18) {   // fused sel: 64 rows per block
        int w = tid >> 5, lane = tid & 31;
        int row0 = blockIdx.y * 64;
        for (int r = w; r < 64; r += 8) {
            int row = row0 + r;
            const float* x = mamba + (size_t)row * CC;
            float s = 0.f, s2 = 0.f;
            for (int c = lane; c < CC; c += 32) { float v = x[c]; s += v; s2 += v * v; }
            #pragma unroll
            for (int o = 16; o; o >>= 1) {
                s  += __shfl_xor_sync(0xffffffffu, s,  o);
                s2 += __shfl_xor_sync(0xffffffffu, s2, o);
            }
            float mu = s / CC, var = s2 / CC - mu * mu, rstd = rsqrtf(var + 1e-5f);
            float dot = 0.f;
            for (int c = lane; c < CC; c += 32)
                dot += ((x[c] - mu) * rstd * lnw[c] + lnb[c]) * selw[c];
            #pragma unroll
            for (int o = 16; o; o >>= 1) dot += __shfl_xor_sync(0xffffffffu, dot, o);
            if (lane == 0) {
                float z = mscale[0] * dot + selb[0];
                g_sel[row] = 1.f / (1.f + __expf(-z));
            }
        }
        return;
    }

    int w = tid >> 5, lane = tid & 31, l7 = lane & 7;
    int wm = (w & 1) * 32, wn = (w >> 1) * 32;
    int m0 = blockIdx.y * 64, n0 = blockIdx.x * 128;
    const int ldw = 3 * CC;
    unsigned base = smem_u32(smh);

    // A loader: 64 rows x 8 chunks(16B); 2 chunks/thread
    int ar = tid >> 2;
    int aSts[2];
    #pragma unroll
    for (int i = 0; i < 2; i++) {
        int c = (tid & 3) * 2 + i;
        aSts[i] = ar * 128 + ((c ^ (ar & 7)) * 16);
    }
    // B loader: 64 rows x 16 chunks; 4 chunks/thread (two 64n subtiles)
    int brr = tid >> 2;
    int bSts[4];
    #pragma unroll
    for (int i = 0; i < 4; i++) {
        int c = (tid & 3) * 4 + i;
        bSts[i] = (c >> 3) * 8192 + brr * 128 + (((c & 7) ^ (brr & 7)) * 16);
    }
    const __half* Asrc = g_x16 + (size_t)(m0 + ar) * CC + (tid & 3) * 16;
    const __half* Bsrc = g_wa16 + (size_t)brr * ldw + n0 + (tid & 3) * 32;

    // ldsm addresses
    int aRowByte = (wm + l7 + 8 * ((lane >> 3) & 1)) * 128;
    int aCc[4];
    #pragma unroll
    for (int kc = 0; kc < 4; kc++)
        aCc[kc] = ((2 * kc + (lane >> 4)) ^ l7) * 16;
    int sSub = ((w >> 1) >> 1) * 8192;
    int cBase = ((w >> 1) & 1) * 4;
    int bRowByte = (l7 + 8 * ((lane >> 3) & 1)) * 128;
    int bCc[2][4];
    #pragma unroll
    for (int ntp = 0; ntp < 2; ntp++)
        #pragma unroll
        for (int kc = 0; kc < 4; kc++)
            bCc[ntp][kc] = kc * 2048 + (((cBase + 2 * ntp + (lane >> 4)) ^ l7) * 16);

    uint4 ra[2], rb[4];
    #define LDG_T(ks) do { \
        const __half* pa = Asrc + (ks) * 64; \
        const __half* pb = Bsrc + (size_t)(ks) * 64 * ldw; \
        ra[0] = *(const uint4*)pa;        ra[1] = *(const uint4*)(pa + 8); \
        rb[0] = *(const uint4*)pb;        rb[1] = *(const uint4*)(pb + 8); \
        rb[2] = *(const uint4*)(pb + 16); rb[3] = *(const uint4*)(pb + 24); \
    } while (0)
    #define STS_T(buf) do { \
        char* sa_ = (char*)smh + (buf) * STG_BYTES; \
        char* sb_ = sa_ + 8192; \
        *(uint4*)(sa_ + aSts[0]) = ra[0]; *(uint4*)(sa_ + aSts[1]) = ra[1]; \
        *(uint4*)(sb_ + bSts[0]) = rb[0]; *(uint4*)(sb_ + bSts[1]) = rb[1]; \
        *(uint4*)(sb_ + bSts[2]) = rb[2]; *(uint4*)(sb_ + bSts[3]) = rb[3]; \
    } while (0)

    LDG_T(0);
    STS_T(0);
    __syncthreads();

    float C[2][4][4] = {};
    const int NK = CC / 64;
    for (int ks = 0; ks < NK; ks++) {
        if (ks + 1 < NK) LDG_T(ks + 1);
        unsigned sA = base + (ks & 1) * STG_BYTES;
        unsigned sB = sA + 8192 + sSub;
        #pragma unroll
        for (int kc = 0; kc < 4; kc++) {
            unsigned bf[2][4];
            #pragma unroll
            for (int ntp = 0; ntp < 2; ntp++)
                ldsm4t(bf[ntp], sB + bRowByte + bCc[ntp][kc]);
            #pragma unroll
            for (int mt = 0; mt < 2; mt++) {
                unsigned af[4];
                ldsm4(af, sA + aRowByte + mt * 2048 + aCc[kc]);
                #pragma unroll
                for (int ntp = 0; ntp < 2; ntp++) {
                    mma_f16(C[mt][2 * ntp],     af[0], af[1], af[2], af[3],
                            bf[ntp][0], bf[ntp][1]);
                    mma_f16(C[mt][2 * ntp + 1], af[0], af[1], af[2], af[3],
                            bf[ntp][2], bf[ntp][3]);
                }
            }
        }
        if (ks + 1 < NK) {
            STS_T((ks + 1) & 1);
            __syncthreads();
        }
    }
    #undef LDG_T
    #undef STS_T

    int g = lane >> 2, t = lane & 3;
    #pragma unroll
    for (int mt = 0; mt < 2; mt++) {
        int m1 = m0 + wm + mt * 16 + g, m2 = m1 + 8;
        int b1_ = m1 >> 11, t1 = m1 & (TT - 1);
        int b2_ = m2 >> 11, t2 = m2 & (TT - 1);
        #pragma unroll
        for (int nt = 0; nt < 4; nt++) {
            int col = n0 + wn + nt * 8 + 2 * t;
            int which = col / CC, rem = col - which * CC;
            int h = rem >> 6, d = rem & 63;
            __half* dst = which == 0 ? g_q : (which == 1 ? g_k : g_v);
            float sc = (which == 0) ? 0.125f : 1.f;
            float bx = bias[col], by = bias[col + 1];
            *(unsigned*)&dst[(((size_t)b1_ * HH + h) * TT + t1) * DD + d] =
                pack2((C[mt][nt][0] + bx) * sc, (C[mt][nt][1] + by) * sc);
            *(unsigned*)&dst[(((size_t)b2_ * HH + h) * TT + t2) * DD + d] =
                pack2((C[mt][nt][2] + bx) * sc, (C[mt][nt][3] + by) * sc);
        }
    }
}

// ---------------- proj GEMM ----------------
__global__ void __launch_bounds__(256, 3) proj_gemm(const float* __restrict__ bias,
                                                    float* __restrict__ out) {
    extern __shared__ __half smh[];
    int tid = threadIdx.x, w = tid >> 5, lane = tid & 31, l7 = lane & 7;
    int wm = (w & 1) * 32, wn = (w >> 1) * 32;
    int m0 = blockIdx.y * 64, n0 = blockIdx.x * 128;
    const int ldw = CC;
    unsigned base = smem_u32(smh);

    int ar = tid >> 2;
    int aSts[2];
    #pragma unroll
    for (int i = 0; i < 2; i++) {
        int c = (tid & 3) * 2 + i;
        aSts[i] = ar * 128 + ((c ^ (ar & 7)) * 16);
    }
    int brr = tid >> 2;
    int bSts[4];
    #pragma unroll
    for (int i = 0; i < 4; i++) {
        int c = (tid & 3) * 4 + i;
        bSts[i] = (c >> 3) * 8192 + brr * 128 + (((c & 7) ^ (brr & 7)) * 16);
    }
    const __half* Asrc = g_att + (size_t)(m0 + ar) * CC + (tid & 3) * 16;
    const __half* Bsrc = g_wp16 + (size_t)brr * ldw + n0 + (tid & 3) * 32;

    int aRowByte = (wm + l7 + 8 * ((lane >> 3) & 1)) * 128;
    int aCc[4];
    #pragma unroll
    for (int kc = 0; kc < 4; kc++)
        aCc[kc] = ((2 * kc + (lane >> 4)) ^ l7) * 16;
    int sSub = ((w >> 1) >> 1) * 8192;
    int cBase = ((w >> 1) & 1) * 4;
    int bRowByte = (l7 + 8 * ((lane >> 3) & 1)) * 128;
    int bCc[2][4];
    #pragma unroll
    for (int ntp = 0; ntp < 2; ntp++)
        #pragma unroll
        for (int kc = 0; kc < 4; kc++)
            bCc[ntp][kc] = kc * 2048 + (((cBase + 2 * ntp + (lane >> 4)) ^ l7) * 16);

    uint4 ra[2], rb[4];
    #define LDG_T(ks) do { \
        const __half* pa = Asrc + (ks) * 64; \
        const __half* pb = Bsrc + (size_t)(ks) * 64 * ldw; \
        ra[0] = *(const uint4*)pa;        ra[1] = *(const uint4*)(pa + 8); \
        rb[0] = *(const uint4*)pb;        rb[1] = *(const uint4*)(pb + 8); \
        rb[2] = *(const uint4*)(pb + 16); rb[3] = *(const uint4*)(pb + 24); \
    } while (0)
    #define STS_T(buf) do { \
        char* sa_ = (char*)smh + (buf) * STG_BYTES; \
        char* sb_ = sa_ + 8192; \
        *(uint4*)(sa_ + aSts[0]) = ra[0]; *(uint4*)(sa_ + aSts[1]) = ra[1]; \
        *(uint4*)(sb_ + bSts[0]) = rb[0]; *(uint4*)(sb_ + bSts[1]) = rb[1]; \
        *(uint4*)(sb_ + bSts[2]) = rb[2]; *(uint4*)(sb_ + bSts[3]) = rb[3]; \
    } while (0)

    LDG_T(0);
    STS_T(0);
    __syncthreads();

    float C[2][4][4] = {};
    const int NK = CC / 64;
    for (int ks = 0; ks < NK; ks++) {
        if (ks + 1 < NK) LDG_T(ks + 1);
        unsigned sA = base + (ks & 1) * STG_BYTES;
        unsigned sB = sA + 8192 + sSub;
        #pragma unroll
        for (int kc = 0; kc < 4; kc++) {
            unsigned bf[2][4];
            #pragma unroll
            for (int ntp = 0; ntp < 2; ntp++)
                ldsm4t(bf[ntp], sB + bRowByte + bCc[ntp][kc]);
            #pragma unroll
            for (int mt = 0; mt < 2; mt++) {
                unsigned af[4];
                ldsm4(af, sA + aRowByte + mt * 2048 + aCc[kc]);
                #pragma unroll
                for (int ntp = 0; ntp < 2; ntp++) {
                    mma_f16(C[mt][2 * ntp],     af[0], af[1], af[2], af[3],
                            bf[ntp][0], bf[ntp][1]);
                    mma_f16(C[mt][2 * ntp + 1], af[0], af[1], af[2], af[3],
                            bf[ntp][2], bf[ntp][3]);
                }
            }
        }
        if (ks + 1 < NK) {
            STS_T((ks + 1) & 1);
            __syncthreads();
        }
    }
    #undef LDG_T
    #undef STS_T

    int g = lane >> 2, t = lane & 3;
    #pragma unroll
    for (int mt = 0; mt < 2; mt++) {
        int m1 = m0 + wm + mt * 16 + g, m2 = m1 + 8;
        #pragma unroll
        for (int nt = 0; nt < 4; nt++) {
            int col = n0 + wn + nt * 8 + 2 * t;
            float bx = bias[col], by = bias[col + 1];
            *(float2*)&out[(size_t)m1 * CC + col] =
                make_float2(C[mt][nt][0] + bx, C[mt][nt][1] + by);
            *(float2*)&out[(size_t)m2 * CC + col] =
                make_float2(C[mt][nt][2] + bx, C[mt][nt][3] + by);
        }
    }
}

// ---------------- fp16 dual flash attention (unchanged, proven in R9/R12) ----------------
#define ATT_SMEM_BYTES (16384 * 2 + 2 * 64 * 4)

__global__ void __launch_bounds__(256) attn_kernel(const float* __restrict__ lw_p,
                                                   const float* __restrict__ gw_p) {
    extern __shared__ __half sh[];
    float* gfb = (float*)(sh + 16384);
    int tid = threadIdx.x, w = tid >> 5, lane = tid & 31;
    int g = lane >> 2, t = lane & 3, l7 = lane & 7, j = lane >> 3;
    int bh = blockIdx.y, b_ = bh / HH, hh = bh % HH;
    int qt = (gridDim.x - 1) - blockIdx.x;
    int q0 = qt << 7;
    const __half* Qp = g_q + (size_t)bh * TT * DD;
    const __half* Kp = g_k + (size_t)bh * TT * DD;
    const __half* Vp = g_v + (size_t)bh * TT * DD;

    int r1 = q0 + 16 * w + g, r2 = r1 + 8;

    unsigned aq[4][4];
    #pragma unroll
    for (int kc = 0; kc < 4; kc++) {
        aq[kc][0] = *(const unsigned*)(Qp + (size_t)r1 * DD + 16 * kc + 2 * t);
        aq[kc][1] = *(const unsigned*)(Qp + (size_t)r2 * DD + 16 * kc + 2 * t);
        aq[kc][2] = *(const unsigned*)(Qp + (size_t)r1 * DD + 16 * kc + 2 * t + 8);
        aq[kc][3] = *(const unsigned*)(Qp + (size_t)r2 * DD + 16 * kc + 2 * t + 8);
    }

    int lrow = tid >> 2, lcq = tid & 3;
    int sts0 = offKV(lrow, 2 * lcq), sts1 = offKV(lrow, 2 * lcq + 1);

    unsigned base = smem_u32(sh);
    unsigned Kb[2] = { base, base + 8192 };
    unsigned Vb[2] = { base + 16384, base + 24576 };
    int kOff0 = l7 * 128 + ((j ^ l7) * 16);
    int kOff1 = l7 * 128 + (((4 + j) ^ l7) * 16);
    int vRow = (8 * (j & 1) + l7) * 128;
    int jh = lane >> 4;
    int vCc[4];
    #pragma unroll
    for (int nvp = 0; nvp < 4; nvp++) vCc[nvp] = ((2 * nvp + jh) ^ l7) * 16;

    {
        uint4 k0a = *(const uint4*)(Kp + (size_t)lrow * DD + 16 * lcq);
        uint4 k0b = *(const uint4*)(Kp + (size_t)lrow * DD + 16 * lcq + 8);
        uint4 v0a = *(const uint4*)(Vp + (size_t)lrow * DD + 16 * lcq);
        uint4 v0b = *(const uint4*)(Vp + (size_t)lrow * DD + 16 * lcq + 8);
        *(uint4*)&sh[sts0] = k0a;           *(uint4*)&sh[sts1] = k0b;
        *(uint4*)&sh[8192 + sts0] = v0a;    *(uint4*)&sh[8192 + sts1] = v0b;
        if (tid < 64) gfb[tid] = 0.5f + 0.5f * g_sel[b_ * TT + tid];
    }
    __syncthreads();

    float accG[8][4] = {}, accL[8][4] = {};
    float lg1 = 0.f, lg2 = 0.f, ll1 = 0.f, ll2 = 0.f;

    int ktmax = 2 * qt + 1;
    for (int kt = 0; kt <= ktmax; kt++) {
        int k0 = kt << 6;
        int p = kt & 1;
        const float* cG = gfb + p * 64;
        bool wAct = (k0 <= q0 + 16 * w + 15);
        bool lAct = wAct && (k0 + 63 >= q0 + 16 * w - WIN);

        float Cs[8][4] = {};
        if (wAct) {
            #pragma unroll
            for (int nt = 0; nt < 8; nt++) {
                unsigned bq[4], bq2[4];
                ldsm4(bq,  Kb[p] + nt * 1024 + kOff0);
                ldsm4(bq2, Kb[p] + nt * 1024 + kOff1);
                mma_f16(Cs[nt], aq[0][0], aq[0][1], aq[0][2], aq[0][3], bq[0],  bq[1]);
                mma_f16(Cs[nt], aq[1][0], aq[1][1], aq[1][2], aq[1][3], bq[2],  bq[3]);
                mma_f16(Cs[nt], aq[2][0], aq[2][1], aq[2][2], aq[2][3], bq2[0], bq2[1]);
                mma_f16(Cs[nt], aq[3][0], aq[3][1], aq[3][2], aq[3][3], bq2[2], bq2[3]);
            }
        }

        uint4 nk0, nk1, nv0, nv1;
        float nsel = 0.f;
        if (kt < ktmax) {
            int kn = (kt + 1) << 6;
            nk0 = *(const uint4*)(Kp + (size_t)(kn + lrow) * DD + 16 * lcq);
            nk1 = *(const uint4*)(Kp + (size_t)(kn + lrow) * DD + 16 * lcq + 8);
            nv0 = *(const uint4*)(Vp + (size_t)(kn + lrow) * DD + 16 * lcq);
            nv1 = *(const uint4*)(Vp + (size_t)(kn + lrow) * DD + 16 * lcq + 8);
            if (tid < 64) nsel = g_sel[b_ * TT + kn + tid];
        }

        if (wAct) {
            unsigned Pg[8][2], Pl[8][2];
            #pragma unroll
            for (int nt = 0; nt < 8; nt++) {
                int c = k0 + 8 * nt + 2 * t;
                float2 gf = *(const float2*)(cG + 8 * nt + 2 * t);
                float s0 = Cs[nt][0], s1 = Cs[nt][1], s2 = Cs[nt][2], s3 = Cs[nt][3];
                float vg0 = (c > r1)     ? NEGBIG : s0 * gf.x;
                float vg1 = (c + 1 > r1) ? NEGBIG : s1 * gf.y;
                float vg2 = (c > r2)     ? NEGBIG : s2 * gf.x;
                float vg3 = (c + 1 > r2) ? NEGBIG : s3 * gf.y;
                float e0 = __expf(vg0), e1 = __expf(vg1);
                float e2 = __expf(vg2), e3 = __expf(vg3);
                lg1 += e0 + e1; lg2 += e2 + e3;
                Pg[nt][0] = pack2(e0, e1);
                Pg[nt][1] = pack2(e2, e3);
                if (lAct) {
                    float vl0 = (c > r1     || c < r1 - WIN)     ? NEGBIG : s0;
                    float vl1 = (c + 1 > r1 || c + 1 < r1 - WIN) ? NEGBIG : s1;
                    float vl2 = (c > r2     || c < r2 - WIN)     ? NEGBIG : s2;
                    float vl3 = (c + 1 > r2 || c + 1 < r2 - WIN) ? NEGBIG : s3;
                    float f0 = __expf(vl0), f1 = __expf(vl1);
                    float f2 = __expf(vl2), f3 = __expf(vl3);
                    ll1 += f0 + f1; ll2 += f2 + f3;
                    Pl[nt][0] = pack2(f0, f1);
                    Pl[nt][1] = pack2(f2, f3);
                }
            }
            #pragma unroll
            for (int kc = 0; kc < 4; kc++) {
                unsigned a0 = Pg[2 * kc][0], a1 = Pg[2 * kc][1];
                unsigned a2 = Pg[2 * kc + 1][0], a3 = Pg[2 * kc + 1][1];
                #pragma unroll
                for (int nvp = 0; nvp < 4; nvp++) {
                    unsigned bv[4];
                    ldsm4t(bv, Vb[p] + kc * 2048 + vRow + vCc[nvp]);
                    mma_f16(accG[2 * nvp],     a0, a1, a2, a3, bv[0], bv[1]);
                    mma_f16(accG[2 * nvp + 1], a0, a1, a2, a3, bv[2], bv[3]);
                    if (lAct) {
                        unsigned c0 = Pl[2 * kc][0], c1 = Pl[2 * kc][1];
                        unsigned c2 = Pl[2 * kc + 1][0], c3 = Pl[2 * kc + 1][1];
                        mma_f16(accL[2 * nvp],     c0, c1, c2, c3, bv[0], bv[1]);
                        mma_f16(accL[2 * nvp + 1], c0, c1, c2, c3, bv[2], bv[3]);
                    }
                }
            }
        }

        if (kt < ktmax) {
            int q_ = p ? 0 : 1;
            *(uint4*)&sh[q_ * 4096 + sts0] = nk0;
            *(uint4*)&sh[q_ * 4096 + sts1] = nk1;
            *(uint4*)&sh[8192 + q_ * 4096 + sts0] = nv0;
            *(uint4*)&sh[8192 + q_ * 4096 + sts1] = nv1;
            if (tid < 64) gfb[(p ? 0 : 64) + tid] = 0.5f + 0.5f * nsel;
        }
        __syncthreads();
    }

    lg1 += __shfl_xor_sync(0xffffffffu, lg1, 1);
    lg1 += __shfl_xor_sync(0xffffffffu, lg1, 2);
    lg2 += __shfl_xor_sync(0xffffffffu, lg2, 1);
    lg2 += __shfl_xor_sync(0xffffffffu, lg2, 2);
    ll1 += __shfl_xor_sync(0xffffffffu, ll1, 1);
    ll1 += __shfl_xor_sync(0xffffffffu, ll1, 2);
    ll2 += __shfl_xor_sync(0xffffffffu, ll2, 1);
    ll2 += __shfl_xor_sync(0xffffffffu, ll2, 2);

    float wl = 1.f / (1.f + __expf(-lw_p[0]));
    float wg = 1.f / (1.f + __expf(-gw_p[0]));
    float wsum = wl + wg; wl /= wsum; wg /= wsum;
    float rg1 = wg / lg1, rg2 = wg / lg2;
    float rl1 = wl / ll1, rl2 = wl / ll2;
    #pragma unroll
    for (int nt = 0; nt < 8; nt++) {
        int d = 8 * nt + 2 * t;
        __half* o1 = &g_att[(((size_t)b_ * TT + r1) * HH + hh) * DD + d];
        __half* o2 = &g_att[(((size_t)b_ * TT + r2) * HH + hh) * DD + d];
        *(unsigned*)o1 = pack2(accL[nt][0] * rl1 + accG[nt][0] * rg1,
                               accL[nt][1] * rl1 + accG[nt][1] * rg1);
        *(unsigned*)o2 = pack2(accL[nt][2] * rl2 + accG[nt][2] * rg2,
                               accL[nt][3] * rl2 + accG[nt][3] * rg2);
    }
}

// ---------------- launch ----------------
extern "C" void kernel_launch(void* const* d_in, const int* in_sizes, int n_in,
                              void* d_out, int out_size) {
    const float* x        = (const float*)d_in[0];
    const float* mamba    = (const float*)d_in[1];
    const float* c_attn_w = (const float*)d_in[2];
    const float* c_attn_b = (const float*)d_in[3];
    const float* c_proj_w = (const float*)d_in[4];
    const float* c_proj_b = (const float*)d_in[5];
    const float* ln_w     = (const float*)d_in[6];
    const float* ln_b     = (const float*)d_in[7];
    const float* mscale   = (const float*)d_in[8];
    const float* sel_w    = (const float*)d_in[9];
    const float* sel_b    = (const float*)d_in[10];
    const float* local_w  = (const float*)d_in[11];
    const float* global_w = (const float*)d_in[12];
    float* out = (float*)d_out;

    cudaFuncSetAttribute((const void*)qkv_gemm,
                         cudaFuncAttributeMaxDynamicSharedMemorySize, GEMM_SMEM_BYTES);
    cudaFuncSetAttribute((const void*)proj_gemm,
                         cudaFuncAttributeMaxDynamicSharedMemorySize, GEMM_SMEM_BYTES);
    cudaFuncSetAttribute((const void*)attn_kernel,
                         cudaFuncAttributeMaxDynamicSharedMemorySize, ATT_SMEM_BYTES);

    cvt_kernel<<<296, 256>>>(x, c_attn_w, c_proj_w);
    qkv_gemm<<<dim3(19, 64), 256, GEMM_SMEM_BYTES>>>(
        c_attn_b, mamba, ln_w, ln_b, sel_w, sel_b, mscale);
    attn_kernel<<<dim3(TT / 128, BB * HH), 256, ATT_SMEM_BYTES>>>(local_w, global_w);
    proj_gemm<<<dim3(6, 64), 256, GEMM_SMEM_BYTES>>>(c_proj_b, out);
}

// round 16
// speedup vs baseline: 1.0932x; 1.0932x over previous
#include <cuda_runtime.h>
#include <cuda_fp16.h>
#include <math.h>

#define BB 2
#define TT 2048
#define CC 768
#define HH 12
#define DD 64
#define WIN 256
#define NEGBIG -1.0e30f
#define LOG2E 1.4426950408889634f

// ---------------- scratch ----------------
__device__ __half g_q[BB*HH*TT*DD];      // pre-scaled by 1/8
__device__ __half g_k[BB*HH*TT*DD];
__device__ __half g_v[BB*HH*TT*DD];
__device__ float  g_sel[BB*TT];
__device__ __half g_att[(size_t)BB*TT*CC];
__device__ __half g_x16[(size_t)BB*TT*CC];
__device__ __half g_wa16[(size_t)CC*3*CC];
__device__ __half g_wp16[(size_t)CC*CC];

// ---------------- helpers ----------------
__device__ __forceinline__ unsigned pack2(float a, float b) {
    __half2 h = __floats2half2_rn(a, b);
    return *(unsigned*)&h;
}
__device__ __forceinline__ unsigned exppack2(float a, float b) {
    __half2 h = h2exp2(__floats2half2_rn(a, b));
    return *(unsigned*)&h;
}
__device__ __forceinline__ unsigned smem_u32(const void* p) {
    return (unsigned)__cvta_generic_to_shared(p);
}
__device__ __forceinline__ void ldsm4(unsigned r[4], unsigned addr) {
    asm volatile("ldmatrix.sync.aligned.m8n8.x4.shared.b16 {%0,%1,%2,%3}, [%4];"
        : "=r"(r[0]), "=r"(r[1]), "=r"(r[2]), "=r"(r[3]) : "r"(addr));
}
__device__ __forceinline__ void ldsm4t(unsigned r[4], unsigned addr) {
    asm volatile("ldmatrix.sync.aligned.m8n8.x4.trans.shared.b16 {%0,%1,%2,%3}, [%4];"
        : "=r"(r[0]), "=r"(r[1]), "=r"(r[2]), "=r"(r[3]) : "r"(addr));
}
__device__ __forceinline__ void mma_f16(float c[4], unsigned a0, unsigned a1,
                                        unsigned a2, unsigned a3,
                                        unsigned b0, unsigned b1) {
    asm volatile(
        "mma.sync.aligned.m16n8k16.row.col.f32.f16.f16.f32 "
        "{%0,%1,%2,%3},{%4,%5,%6,%7},{%8,%9},{%0,%1,%2,%3};"
        : "+f"(c[0]), "+f"(c[1]), "+f"(c[2]), "+f"(c[3])
        : "r"(a0), "r"(a1), "r"(a2), "r"(a3), "r"(b0), "r"(b1));
}

// attn K/V tile 64x64 halves: 128B rows, chunk c in 0..7
__device__ __forceinline__ int offKV(int r, int c) {
    return r * 64 + (c ^ (r & 7)) * 8;
}

// ---------------- fp32 -> fp16 pre-convert ----------------
__global__ void cvt_kernel(const float* __restrict__ X, const float* __restrict__ Wa,
                           const float* __restrict__ Wp) {
    int idx = blockIdx.x * blockDim.x + threadIdx.x;
    int stride = gridDim.x * blockDim.x;
    const int nX = BB * TT * CC / 4, nA = CC * 3 * CC / 4, nP = CC * CC / 4;
    for (int i = idx; i < nX; i += stride) {
        float4 v = ((const float4*)X)[i];
        ((uint2*)g_x16)[i] = make_uint2(pack2(v.x, v.y), pack2(v.z, v.w));
    }
    for (int i = idx; i < nA; i += stride) {
        float4 v = ((const float4*)Wa)[i];
        ((uint2*)g_wa16)[i] = make_uint2(pack2(v.x, v.y), pack2(v.z, v.w));
    }
    for (int i = idx; i < nP; i += stride) {
        float4 v = ((const float4*)Wp)[i];
        ((uint2*)g_wp16)[i] = make_uint2(pack2(v.x, v.y), pack2(v.z, v.w));
    }
}

// ---------------- GEMM: 128x128 block, K-step 64, 2-stage LDG->STS (R12 proven) ----------------
#define STG_BYTES 32768
#define GEMM_SMEM_BYTES (2 * STG_BYTES)   // 64 KB

// ---------------- qkv GEMM + fused sel ----------------
__global__ void __launch_bounds__(256, 2) qkv_gemm(
    const float* __restrict__ bias,
    const float* __restrict__ mamba, const float* __restrict__ lnw, const float* __restrict__ lnb,
    const float* __restrict__ selw, const float* __restrict__ selb, const float* __restrict__ mscale)
{
    extern __shared__ __half smh[];
    int tid = threadIdx.x;

    if (blockIdx.x == 18) {   // fused sel
        int w = tid >> 5, lane = tid & 31;
        int row0 = blockIdx.y * 128;
        for (int r = w; r < 128; r += 8) {
            int row = row0 + r;
            const float* x = mamba + (size_t)row * CC;
            float s = 0.f, s2 = 0.f;
            for (int c = lane; c < CC; c += 32) { float v = x[c]; s += v; s2 += v * v; }
            #pragma unroll
            for (int o = 16; o; o >>= 1) {
                s  += __shfl_xor_sync(0xffffffffu, s,  o);
                s2 += __shfl_xor_sync(0xffffffffu, s2, o);
            }
            float mu = s / CC, var = s2 / CC - mu * mu, rstd = rsqrtf(var + 1e-5f);
            float dot = 0.f;
            for (int c = lane; c < CC; c += 32)
                dot += ((x[c] - mu) * rstd * lnw[c] + lnb[c]) * selw[c];
            #pragma unroll
            for (int o = 16; o; o >>= 1) dot += __shfl_xor_sync(0xffffffffu, dot, o);
            if (lane == 0) {
                float z = mscale[0] * dot + selb[0];
                g_sel[row] = 1.f / (1.f + __expf(-z));
            }
        }
        return;
    }

    int w = tid >> 5, lane = tid & 31, l7 = lane & 7;
    int wm = (w & 1) * 64, wn = (w >> 1) * 32;
    int m0 = blockIdx.y * 128, n0 = blockIdx.x * 128;
    const int ldw = 3 * CC;
    unsigned base = smem_u32(smh);

    int ar = tid >> 1;
    int aSts[4];
    #pragma unroll
    for (int i = 0; i < 4; i++) {
        int c = (tid & 1) * 4 + i;
        aSts[i] = ar * 128 + ((c ^ (ar & 7)) * 16);
    }
    int brr = tid >> 2;
    int bSts[4];
    #pragma unroll
    for (int i = 0; i < 4; i++) {
        int c = (tid & 3) * 4 + i;
        bSts[i] = (c >> 3) * 8192 + brr * 128 + (((c & 7) ^ (brr & 7)) * 16);
    }
    const __half* Asrc = g_x16 + (size_t)(m0 + ar) * CC + (tid & 1) * 32;
    const __half* Bsrc = g_wa16 + (size_t)brr * ldw + n0 + (tid & 3) * 32;

    int aRowByte = (wm + l7 + 8 * ((lane >> 3) & 1)) * 128;
    int aCc[4];
    #pragma unroll
    for (int kc = 0; kc < 4; kc++)
        aCc[kc] = ((2 * kc + (lane >> 4)) ^ l7) * 16;
    int sSub = ((w >> 1) >> 1) * 8192;
    int cBase = ((w >> 1) & 1) * 4;
    int bRowByte = (l7 + 8 * ((lane >> 3) & 1)) * 128;
    int bCc[2][4];
    #pragma unroll
    for (int ntp = 0; ntp < 2; ntp++)
        #pragma unroll
        for (int kc = 0; kc < 4; kc++)
            bCc[ntp][kc] = kc * 2048 + (((cBase + 2 * ntp + (lane >> 4)) ^ l7) * 16);

    uint4 ra[4], rb[4];
    #define LDG_T(ks) do { \
        const __half* pa = Asrc + (ks) * 64; \
        const __half* pb = Bsrc + (size_t)(ks) * 64 * ldw; \
        ra[0] = *(const uint4*)pa;        ra[1] = *(const uint4*)(pa + 8); \
        ra[2] = *(const uint4*)(pa + 16); ra[3] = *(const uint4*)(pa + 24); \
        rb[0] = *(const uint4*)pb;        rb[1] = *(const uint4*)(pb + 8); \
        rb[2] = *(const uint4*)(pb + 16); rb[3] = *(const uint4*)(pb + 24); \
    } while (0)
    #define STS_T(buf) do { \
        char* sa_ = (char*)smh + (buf) * STG_BYTES; \
        char* sb_ = sa_ + 16384; \
        *(uint4*)(sa_ + aSts[0]) = ra[0]; *(uint4*)(sa_ + aSts[1]) = ra[1]; \
        *(uint4*)(sa_ + aSts[2]) = ra[2]; *(uint4*)(sa_ + aSts[3]) = ra[3]; \
        *(uint4*)(sb_ + bSts[0]) = rb[0]; *(uint4*)(sb_ + bSts[1]) = rb[1]; \
        *(uint4*)(sb_ + bSts[2]) = rb[2]; *(uint4*)(sb_ + bSts[3]) = rb[3]; \
    } while (0)

    LDG_T(0);
    STS_T(0);
    __syncthreads();

    float C[4][4][4] = {};
    const int NK = CC / 64;
    for (int ks = 0; ks < NK; ks++) {
        if (ks + 1 < NK) LDG_T(ks + 1);
        unsigned sA = base + (ks & 1) * STG_BYTES;
        unsigned sB = sA + 16384 + sSub;
        #pragma unroll
        for (int kc = 0; kc < 4; kc++) {
            unsigned bf[2][4];
            #pragma unroll
            for (int ntp = 0; ntp < 2; ntp++)
                ldsm4t(bf[ntp], sB + bRowByte + bCc[ntp][kc]);
            #pragma unroll
            for (int mt = 0; mt < 4; mt++) {
                unsigned af[4];
                ldsm4(af, sA + aRowByte + mt * 2048 + aCc[kc]);
                #pragma unroll
                for (int ntp = 0; ntp < 2; ntp++) {
                    mma_f16(C[mt][2 * ntp],     af[0], af[1], af[2], af[3],
                            bf[ntp][0], bf[ntp][1]);
                    mma_f16(C[mt][2 * ntp + 1], af[0], af[1], af[2], af[3],
                            bf[ntp][2], bf[ntp][3]);
                }
            }
        }
        if (ks + 1 < NK) {
            STS_T((ks + 1) & 1);
            __syncthreads();
        }
    }
    #undef LDG_T
    #undef STS_T

    int g = lane >> 2, t = lane & 3;
    #pragma unroll
    for (int mt = 0; mt < 4; mt++) {
        int m1 = m0 + wm + mt * 16 + g, m2 = m1 + 8;
        int b1_ = m1 >> 11, t1 = m1 & (TT - 1);
        int b2_ = m2 >> 11, t2 = m2 & (TT - 1);
        #pragma unroll
        for (int nt = 0; nt < 4; nt++) {
            int col = n0 + wn + nt * 8 + 2 * t;
            int which = col / CC, rem = col - which * CC;
            int h = rem >> 6, d = rem & 63;
            __half* dst = which == 0 ? g_q : (which == 1 ? g_k : g_v);
            float sc = (which == 0) ? 0.125f : 1.f;
            float bx = bias[col], by = bias[col + 1];
            *(unsigned*)&dst[(((size_t)b1_ * HH + h) * TT + t1) * DD + d] =
                pack2((C[mt][nt][0] + bx) * sc, (C[mt][nt][1] + by) * sc);
            *(unsigned*)&dst[(((size_t)b2_ * HH + h) * TT + t2) * DD + d] =
                pack2((C[mt][nt][2] + bx) * sc, (C[mt][nt][3] + by) * sc);
        }
    }
}

// ---------------- proj GEMM ----------------
__global__ void __launch_bounds__(256, 2) proj_gemm(const float* __restrict__ bias,
                                                    float* __restrict__ out) {
    extern __shared__ __half smh[];
    int tid = threadIdx.x, w = tid >> 5, lane = tid & 31, l7 = lane & 7;
    int wm = (w & 1) * 64, wn = (w >> 1) * 32;
    int m0 = blockIdx.y * 128, n0 = blockIdx.x * 128;
    const int ldw = CC;
    unsigned base = smem_u32(smh);

    int ar = tid >> 1;
    int aSts[4];
    #pragma unroll
    for (int i = 0; i < 4; i++) {
        int c = (tid & 1) * 4 + i;
        aSts[i] = ar * 128 + ((c ^ (ar & 7)) * 16);
    }
    int brr = tid >> 2;
    int bSts[4];
    #pragma unroll
    for (int i = 0; i < 4; i++) {
        int c = (tid & 3) * 4 + i;
        bSts[i] = (c >> 3) * 8192 + brr * 128 + (((c & 7) ^ (brr & 7)) * 16);
    }
    const __half* Asrc = g_att + (size_t)(m0 + ar) * CC + (tid & 1) * 32;
    const __half* Bsrc = g_wp16 + (size_t)brr * ldw + n0 + (tid & 3) * 32;

    int aRowByte = (wm + l7 + 8 * ((lane >> 3) & 1)) * 128;
    int aCc[4];
    #pragma unroll
    for (int kc = 0; kc < 4; kc++)
        aCc[kc] = ((2 * kc + (lane >> 4)) ^ l7) * 16;
    int sSub = ((w >> 1) >> 1) * 8192;
    int cBase = ((w >> 1) & 1) * 4;
    int bRowByte = (l7 + 8 * ((lane >> 3) & 1)) * 128;
    int bCc[2][4];
    #pragma unroll
    for (int ntp = 0; ntp < 2; ntp++)
        #pragma unroll
        for (int kc = 0; kc < 4; kc++)
            bCc[ntp][kc] = kc * 2048 + (((cBase + 2 * ntp + (lane >> 4)) ^ l7) * 16);

    uint4 ra[4], rb[4];
    #define LDG_T(ks) do { \
        const __half* pa = Asrc + (ks) * 64; \
        const __half* pb = Bsrc + (size_t)(ks) * 64 * ldw; \
        ra[0] = *(const uint4*)pa;        ra[1] = *(const uint4*)(pa + 8); \
        ra[2] = *(const uint4*)(pa + 16); ra[3] = *(const uint4*)(pa + 24); \
        rb[0] = *(const uint4*)pb;        rb[1] = *(const uint4*)(pb + 8); \
        rb[2] = *(const uint4*)(pb + 16); rb[3] = *(const uint4*)(pb + 24); \
    } while (0)
    #define STS_T(buf) do { \
        char* sa_ = (char*)smh + (buf) * STG_BYTES; \
        char* sb_ = sa_ + 16384; \
        *(uint4*)(sa_ + aSts[0]) = ra[0]; *(uint4*)(sa_ + aSts[1]) = ra[1]; \
        *(uint4*)(sa_ + aSts[2]) = ra[2]; *(uint4*)(sa_ + aSts[3]) = ra[3]; \
        *(uint4*)(sb_ + bSts[0]) = rb[0]; *(uint4*)(sb_ + bSts[1]) = rb[1]; \
        *(uint4*)(sb_ + bSts[2]) = rb[2]; *(uint4*)(sb_ + bSts[3]) = rb[3]; \
    } while (0)

    LDG_T(0);
    STS_T(0);
    __syncthreads();

    float C[4][4][4] = {};
    const int NK = CC / 64;
    for (int ks = 0; ks < NK; ks++) {
        if (ks + 1 < NK) LDG_T(ks + 1);
        unsigned sA = base + (ks & 1) * STG_BYTES;
        unsigned sB = sA + 16384 + sSub;
        #pragma unroll
        for (int kc = 0; kc < 4; kc++) {
            unsigned bf[2][4];
            #pragma unroll
            for (int ntp = 0; ntp < 2; ntp++)
                ldsm4t(bf[ntp], sB + bRowByte + bCc[ntp][kc]);
            #pragma unroll
            for (int mt = 0; mt < 4; mt++) {
                unsigned af[4];
                ldsm4(af, sA + aRowByte + mt * 2048 + aCc[kc]);
                #pragma unroll
                for (int ntp = 0; ntp < 2; ntp++) {
                    mma_f16(C[mt][2 * ntp],     af[0], af[1], af[2], af[3],
                            bf[ntp][0], bf[ntp][1]);
                    mma_f16(C[mt][2 * ntp + 1], af[0], af[1], af[2], af[3],
                            bf[ntp][2], bf[ntp][3]);
                }
            }
        }
        if (ks + 1 < NK) {
            STS_T((ks + 1) & 1);
            __syncthreads();
        }
    }
    #undef LDG_T
    #undef STS_T

    int g = lane >> 2, t = lane & 3;
    #pragma unroll
    for (int mt = 0; mt < 4; mt++) {
        int m1 = m0 + wm + mt * 16 + g, m2 = m1 + 8;
        #pragma unroll
        for (int nt = 0; nt < 4; nt++) {
            int col = n0 + wn + nt * 8 + 2 * t;
            float bx = bias[col], by = bias[col + 1];
            *(float2*)&out[(size_t)m1 * CC + col] =
                make_float2(C[mt][nt][0] + bx, C[mt][nt][1] + by);
            *(float2*)&out[(size_t)m2 * CC + col] =
                make_float2(C[mt][nt][2] + bx, C[mt][nt][3] + by);
        }
    }
}

// ---------------- fp16 dual flash attention: exp2-in-half2 + ones-mma row sums ----------------
#define ATT_SMEM_BYTES (16384 * 2 + 2 * 64 * 4)

__global__ void __launch_bounds__(256) attn_kernel(const float* __restrict__ lw_p,
                                                   const float* __restrict__ gw_p) {
    extern __shared__ __half sh[];
    float* gfb = (float*)(sh + 16384);
    int tid = threadIdx.x, w = tid >> 5, lane = tid & 31;
    int g = lane >> 2, t = lane & 3, l7 = lane & 7, j = lane >> 3;
    int bh = blockIdx.y, b_ = bh / HH, hh = bh % HH;
    int qt = (gridDim.x - 1) - blockIdx.x;
    int q0 = qt << 7;
    const __half* Qp = g_q + (size_t)bh * TT * DD;
    const __half* Kp = g_k + (size_t)bh * TT * DD;
    const __half* Vp = g_v + (size_t)bh * TT * DD;
    const unsigned ONE2 = 0x3C003C00u;    // half2(1.0, 1.0)

    int r1 = q0 + 16 * w + g, r2 = r1 + 8;

    unsigned aq[4][4];
    #pragma unroll
    for (int kc = 0; kc < 4; kc++) {
        aq[kc][0] = *(const unsigned*)(Qp + (size_t)r1 * DD + 16 * kc + 2 * t);
        aq[kc][1] = *(const unsigned*)(Qp + (size_t)r2 * DD + 16 * kc + 2 * t);
        aq[kc][2] = *(const unsigned*)(Qp + (size_t)r1 * DD + 16 * kc + 2 * t + 8);
        aq[kc][3] = *(const unsigned*)(Qp + (size_t)r2 * DD + 16 * kc + 2 * t + 8);
    }

    int lrow = tid >> 2, lcq = tid & 3;
    int sts0 = offKV(lrow, 2 * lcq), sts1 = offKV(lrow, 2 * lcq + 1);

    unsigned base = smem_u32(sh);
    unsigned Kb[2] = { base, base + 8192 };
    unsigned Vb[2] = { base + 16384, base + 24576 };
    int kOff0 = l7 * 128 + ((j ^ l7) * 16);
    int kOff1 = l7 * 128 + (((4 + j) ^ l7) * 16);
    int vRow = (8 * (j & 1) + l7) * 128;
    int jh = lane >> 4;
    int vCc[4];
    #pragma unroll
    for (int nvp = 0; nvp < 4; nvp++) vCc[nvp] = ((2 * nvp + jh) ^ l7) * 16;

    {
        uint4 k0a = *(const uint4*)(Kp + (size_t)lrow * DD + 16 * lcq);
        uint4 k0b = *(const uint4*)(Kp + (size_t)lrow * DD + 16 * lcq + 8);
        uint4 v0a = *(const uint4*)(Vp + (size_t)lrow * DD + 16 * lcq);
        uint4 v0b = *(const uint4*)(Vp + (size_t)lrow * DD + 16 * lcq + 8);
        *(uint4*)&sh[sts0] = k0a;           *(uint4*)&sh[sts1] = k0b;
        *(uint4*)&sh[8192 + sts0] = v0a;    *(uint4*)&sh[8192 + sts1] = v0b;
        if (tid < 64) gfb[tid] = (0.5f + 0.5f * g_sel[b_ * TT + tid]) * LOG2E;
    }
    __syncthreads();

    float accG[8][4] = {}, accL[8][4] = {};
    float sumG[4] = {}, sumL[4] = {};       // row sums via ones-mma (C layout)

    int ktmax = 2 * qt + 1;
    for (int kt = 0; kt <= ktmax; kt++) {
        int k0 = kt << 6;
        int p = kt & 1;
        const float* cG = gfb + p * 64;
        bool wAct = (k0 <= q0 + 16 * w + 15);
        bool lAct = wAct && (k0 + 63 >= q0 + 16 * w - WIN);

        float Cs[8][4] = {};
        if (wAct) {
            #pragma unroll
            for (int nt = 0; nt < 8; nt++) {
                unsigned bq[4], bq2[4];
                ldsm4(bq,  Kb[p] + nt * 1024 + kOff0);
                ldsm4(bq2, Kb[p] + nt * 1024 + kOff1);
                mma_f16(Cs[nt], aq[0][0], aq[0][1], aq[0][2], aq[0][3], bq[0],  bq[1]);
                mma_f16(Cs[nt], aq[1][0], aq[1][1], aq[1][2], aq[1][3], bq[2],  bq[3]);
                mma_f16(Cs[nt], aq[2][0], aq[2][1], aq[2][2], aq[2][3], bq2[0], bq2[1]);
                mma_f16(Cs[nt], aq[3][0], aq[3][1], aq[3][2], aq[3][3], bq2[2], bq2[3]);
            }
        }

        uint4 nk0, nk1, nv0, nv1;
        float nsel = 0.f;
        if (kt < ktmax) {
            int kn = (kt + 1) << 6;
            nk0 = *(const uint4*)(Kp + (size_t)(kn + lrow) * DD + 16 * lcq);
            nk1 = *(const uint4*)(Kp + (size_t)(kn + lrow) * DD + 16 * lcq + 8);
            nv0 = *(const uint4*)(Vp + (size_t)(kn + lrow) * DD + 16 * lcq);
            nv1 = *(const uint4*)(Vp + (size_t)(kn + lrow) * DD + 16 * lcq + 8);
            if (kt < ktmax && tid < 64) nsel = g_sel[b_ * TT + kn + tid];
        }

        if (wAct) {
            // mask + exp2(half2) in C-layout; P lands directly in A-frag order
            unsigned Pg[8][2], Pl[8][2];
            #pragma unroll
            for (int nt = 0; nt < 8; nt++) {
                int c = k0 + 8 * nt + 2 * t;
                float2 gf = *(const float2*)(cG + 8 * nt + 2 * t);   // (0.5+0.5 sel)*log2e
                float s0 = Cs[nt][0], s1 = Cs[nt][1], s2 = Cs[nt][2], s3 = Cs[nt][3];
                float vg0 = (c > r1)     ? NEGBIG : s0 * gf.x;
                float vg1 = (c + 1 > r1) ? NEGBIG : s1 * gf.y;
                float vg2 = (c > r2)     ? NEGBIG : s2 * gf.x;
                float vg3 = (c + 1 > r2) ? NEGBIG : s3 * gf.y;
                Pg[nt][0] = exppack2(vg0, vg1);
                Pg[nt][1] = exppack2(vg2, vg3);
                if (lAct) {
                    float vl0 = (c > r1     || c < r1 - WIN)     ? NEGBIG : s0 * LOG2E;
                    float vl1 = (c + 1 > r1 || c + 1 < r1 - WIN) ? NEGBIG : s1 * LOG2E;
                    float vl2 = (c > r2     || c < r2 - WIN)     ? NEGBIG : s2 * LOG2E;
                    float vl3 = (c + 1 > r2 || c + 1 < r2 - WIN) ? NEGBIG : s3 * LOG2E;
                    Pl[nt][0] = exppack2(vl0, vl1);
                    Pl[nt][1] = exppack2(vl2, vl3);
                }
            }
            #pragma unroll
            for (int kc = 0; kc < 4; kc++) {
                unsigned a0 = Pg[2 * kc][0], a1 = Pg[2 * kc][1];
                unsigned a2 = Pg[2 * kc + 1][0], a3 = Pg[2 * kc + 1][1];
                #pragma unroll
                for (int nvp = 0; nvp < 4; nvp++) {
                    unsigned bv[4];
                    ldsm4t(bv, Vb[p] + kc * 2048 + vRow + vCc[nvp]);
                    mma_f16(accG[2 * nvp],     a0, a1, a2, a3, bv[0], bv[1]);
                    mma_f16(accG[2 * nvp + 1], a0, a1, a2, a3, bv[2], bv[3]);
                    if (lAct) {
                        unsigned c0 = Pl[2 * kc][0], c1 = Pl[2 * kc][1];
                        unsigned c2 = Pl[2 * kc + 1][0], c3 = Pl[2 * kc + 1][1];
                        mma_f16(accL[2 * nvp],     c0, c1, c2, c3, bv[0], bv[1]);
                        mma_f16(accL[2 * nvp + 1], c0, c1, c2, c3, bv[2], bv[3]);
                    }
                }
                // row sums: P @ ones
                mma_f16(sumG, a0, a1, a2, a3, ONE2, ONE2);
                if (lAct) {
                    unsigned c0 = Pl[2 * kc][0], c1 = Pl[2 * kc][1];
                    unsigned c2 = Pl[2 * kc + 1][0], c3 = Pl[2 * kc + 1][1];
                    mma_f16(sumL, c0, c1, c2, c3, ONE2, ONE2);
                }
            }
        }

        if (kt < ktmax) {
            int q_ = p ? 0 : 1;
            *(uint4*)&sh[q_ * 4096 + sts0] = nk0;
            *(uint4*)&sh[q_ * 4096 + sts1] = nk1;
            *(uint4*)&sh[8192 + q_ * 4096 + sts0] = nv0;
            *(uint4*)&sh[8192 + q_ * 4096 + sts1] = nv1;
            if (tid < 64) gfb[(p ? 0 : 64) + tid] = (0.5f + 0.5f * nsel) * LOG2E;
        }
        __syncthreads();
    }

    // epilogue: row sums already per-thread in sum frags (all n-columns identical)
    float lg1 = sumG[0], lg2 = sumG[2];
    float ll1 = sumL[0], ll2 = sumL[2];

    float wl = 1.f / (1.f + __expf(-lw_p[0]));
    float wg = 1.f / (1.f + __expf(-gw_p[0]));
    float wsum = wl + wg; wl /= wsum; wg /= wsum;
    float rg1 = wg / lg1, rg2 = wg / lg2;
    float rl1 = wl / ll1, rl2 = wl / ll2;
    #pragma unroll
    for (int nt = 0; nt < 8; nt++) {
        int d = 8 * nt + 2 * t;
        __half* o1 = &g_att[(((size_t)b_ * TT + r1) * HH + hh) * DD + d];
        __half* o2 = &g_att[(((size_t)b_ * TT + r2) * HH + hh) * DD + d];
        *(unsigned*)o1 = pack2(accL[nt][0] * rl1 + accG[nt][0] * rg1,
                               accL[nt][1] * rl1 + accG[nt][1] * rg1);
        *(unsigned*)o2 = pack2(accL[nt][2] * rl2 + accG[nt][2] * rg2,
                               accL[nt][3] * rl2 + accG[nt][3] * rg2);
    }
}

// ---------------- launch ----------------
extern "C" void kernel_launch(void* const* d_in, const int* in_sizes, int n_in,
                              void* d_out, int out_size) {
    const float* x        = (const float*)d_in[0];
    const float* mamba    = (const float*)d_in[1];
    const float* c_attn_w = (const float*)d_in[2];
    const float* c_attn_b = (const float*)d_in[3];
    const float* c_proj_w = (const float*)d_in[4];
    const float* c_proj_b = (const float*)d_in[5];
    const float* ln_w     = (const float*)d_in[6];
    const float* ln_b     = (const float*)d_in[7];
    const float* mscale   = (const float*)d_in[8];
    const float* sel_w    = (const float*)d_in[9];
    const float* sel_b    = (const float*)d_in[10];
    const float* local_w  = (const float*)d_in[11];
    const float* global_w = (const float*)d_in[12];
    float* out = (float*)d_out;

    cudaFuncSetAttribute((const void*)qkv_gemm,
                         cudaFuncAttributeMaxDynamicSharedMemorySize, GEMM_SMEM_BYTES);
    cudaFuncSetAttribute((const void*)proj_gemm,
                         cudaFuncAttributeMaxDynamicSharedMemorySize, GEMM_SMEM_BYTES);
    cudaFuncSetAttribute((const void*)attn_kernel,
                         cudaFuncAttributeMaxDynamicSharedMemorySize, ATT_SMEM_BYTES);

    cvt_kernel<<<296, 256>>>(x, c_attn_w, c_proj_w);
    qkv_gemm<<<dim3(19, 32), 256, GEMM_SMEM_BYTES>>>(
        c_attn_b, mamba, ln_w, ln_b, sel_w, sel_b, mscale);
    attn_kernel<<<dim3(TT / 128, BB * HH), 256, ATT_SMEM_BYTES>>>(local_w, global_w);
    proj_gemm<<<dim3(6, 32), 256, GEMM_SMEM_BYTES>>>(c_proj_b, out);
}